// round 4
// baseline (speedup 1.0000x reference)
#include <cuda_runtime.h>
#include <math.h>
#include <float.h>

#define N_B   32
#define N_F   80
#define KLEN  251
#define T_IN  32000
#define T_OUT (T_IN - KLEN + 1)   /* 31750 */
#define T_TILE 256
#define F_TILE 16
#define KPAD   252                /* padded filter row in smem */

// Built filter bank lives in a static device global (no allocations allowed).
__device__ float g_filt[N_F * KLEN];

// ---------------------------------------------------------------------------
// Kernel 1: build the 80 x 251 sinc band-pass filter bank.
// One block per filter, 256 threads (251 active taps).
// ---------------------------------------------------------------------------
__global__ void build_filters_k(const float* __restrict__ b1,
                                const float* __restrict__ band)
{
    const int f = blockIdx.x;
    const int i = threadIdx.x;
    __shared__ float red[256];

    const float min_f   = 50.0f / 16000.0f;
    const float beg     = fabsf(b1[f])   + min_f;
    const float endf    = beg + fabsf(band[f]) + min_f;
    const float twopi   = 6.283185307179586f;

    float bp = 0.0f;
    float v  = -FLT_MAX;
    if (i < KLEN) {
        const int d = i - 125;          // distance from center tap
        float sb, se;
        if (d == 0) {
            sb = 1.0f; se = 1.0f;
        } else {
            // t_right[j] = (j+1)/FS ; |d| = j+1 for off-center taps
            const float tr = fabsf((float)d) * (1.0f / 16000.0f);
            const float ab = twopi * (beg  * 16000.0f) * tr;
            const float ae = twopi * (endf * 16000.0f) * tr;
            sb = sinf(ab) / ab;
            se = sinf(ae) / ae;
        }
        bp = 2.0f * endf * se - 2.0f * beg * sb;
        v  = bp;
    }
    red[i] = v;
    __syncthreads();
    #pragma unroll
    for (int s = 128; s > 0; s >>= 1) {
        if (i < s) red[i] = fmaxf(red[i], red[i + s]);
        __syncthreads();
    }
    const float mx = red[0];

    if (i < KLEN) {
        // window: n_i = 251*i/250 ; w = 0.54 - 0.46*cos(2*pi*n_i/251)
        const float n = (251.0f * (float)i) / 250.0f;
        const float w = 0.54f - 0.46f * cosf(twopi * n / 251.0f);
        g_filt[f * KLEN + i] = (bp / mx) * w;
    }
}

// ---------------------------------------------------------------------------
// Kernel 2: valid 1-D correlation, out[b][f][t] = sum_k x[b][t+k]*h[f][k].
// Block tile: T_TILE=256 times x F_TILE=16 filters. 256 threads.
// Thread tile: 4 times (stride 64) x 4 filters. x LDS conflict-free,
// filter LDS broadcast (one warp = one filter group).
// ---------------------------------------------------------------------------
__global__ void __launch_bounds__(256)
sinc_conv_k(const float* __restrict__ x, float* __restrict__ out)
{
    __shared__ float xs[T_TILE + KLEN - 1];   // 506 floats
    __shared__ float fs[F_TILE][KPAD];        // 16 x 252 floats

    const int b   = blockIdx.z;
    const int fb  = blockIdx.y * F_TILE;
    const int t0  = blockIdx.x * T_TILE;
    const int tid = threadIdx.x;

    // --- stage x tile (zero-pad past end of signal) ---
    const float* xb = x + (size_t)b * T_IN;
    for (int i = tid; i < T_TILE + KLEN - 1; i += 256) {
        const int gi = t0 + i;
        xs[i] = (gi < T_IN) ? xb[gi] : 0.0f;
    }
    // --- stage filter tile ---
    for (int i = tid; i < F_TILE * KLEN; i += 256) {
        const int ff = i / KLEN;
        const int kk = i - ff * KLEN;
        fs[ff][kk] = g_filt[(fb + ff) * KLEN + kk];
    }
    __syncthreads();

    const int tx = tid & 63;    // time index within tile (lane-consecutive)
    const int ty = tid >> 6;    // filter group 0..3 (constant within a warp)

    float acc[4][4];
    #pragma unroll
    for (int i = 0; i < 4; i++)
        #pragma unroll
        for (int j = 0; j < 4; j++)
            acc[i][j] = 0.0f;

    const float* xp = &xs[tx];
    const int    f4 = ty * 4;

    #pragma unroll 4
    for (int k = 0; k < KLEN; k++) {
        const float xv0 = xp[k];
        const float xv1 = xp[k + 64];
        const float xv2 = xp[k + 128];
        const float xv3 = xp[k + 192];
        const float h0 = fs[f4 + 0][k];
        const float h1 = fs[f4 + 1][k];
        const float h2 = fs[f4 + 2][k];
        const float h3 = fs[f4 + 3][k];

        acc[0][0] += xv0 * h0;  acc[0][1] += xv0 * h1;
        acc[0][2] += xv0 * h2;  acc[0][3] += xv0 * h3;
        acc[1][0] += xv1 * h0;  acc[1][1] += xv1 * h1;
        acc[1][2] += xv1 * h2;  acc[1][3] += xv1 * h3;
        acc[2][0] += xv2 * h0;  acc[2][1] += xv2 * h1;
        acc[2][2] += xv2 * h2;  acc[2][3] += xv2 * h3;
        acc[3][0] += xv3 * h0;  acc[3][1] += xv3 * h1;
        acc[3][2] += xv3 * h2;  acc[3][3] += xv3 * h3;
    }

    // --- store (coalesced in t across lanes) ---
    #pragma unroll
    for (int j = 0; j < 4; j++) {
        const int f = fb + f4 + j;
        float* op = out + ((size_t)b * N_F + f) * T_OUT;
        #pragma unroll
        for (int i = 0; i < 4; i++) {
            const int t = t0 + tx + 64 * i;
            if (t < T_OUT) op[t] = acc[i][j];
        }
    }
}

extern "C" void kernel_launch(void* const* d_in, const int* in_sizes, int n_in,
                              void* d_out, int out_size)
{
    const float* x    = (const float*)d_in[0];
    const float* b1   = (const float*)d_in[1];
    const float* band = (const float*)d_in[2];
    float* out = (float*)d_out;

    build_filters_k<<<N_F, 256>>>(b1, band);

    dim3 grid((T_OUT + T_TILE - 1) / T_TILE, N_F / F_TILE, N_B);
    sinc_conv_k<<<grid, 256>>>(x, out);
}